// round 8
// baseline (speedup 1.0000x reference)
#include <cuda_runtime.h>

// Fixed problem shapes
#define Tt 2000
#define Bb 64
#define Vv 163
#define Lmax 200
#define NEGV (-1e30f)
#define LOG2E 1.4426950408889634f
#define LN2 0.6931471805599453f

// Superstep config: 9 warps, 1 pair/lane, 9-pair halo = 9 steps per barrier
#define UU 9
#define NWARP 9
#define HALO 9
#define OWNW 23              // 32 - HALO owned pairs per warp; 9*23=207 >= 201
#define NSNAP 208
#define RSTR 164             // padded row stride (floats)
#define THR (NWARP * 32)     // 288
#define NSTG 6               // ceil(UU*Vv / THR) = ceil(1467/288)

// Static device scratch
__device__ float g_lse2[Bb * Tt];   // transposed [b][t]
__device__ float g_llraw[Bb];
__device__ float g_losses[Bb];

__device__ __forceinline__ float ex2f_(float x) {
    float y; asm("ex2.approx.f32 %0, %1;" : "=f"(y) : "f"(x)); return y;
}
__device__ __forceinline__ float lg2f_(float x) {
    float y; asm("lg2.approx.f32 %0, %1;" : "=f"(y) : "f"(x)); return y;
}
__device__ __forceinline__ float lae2_(float a, float b) {
    float M = fmaxf(a, b), m = fminf(a, b);
    return M + lg2f_(1.0f + ex2f_(m - M));
}

// ---------------------------------------------------------------------------
// Kernel 1: per-(t,b) log2-sum-exp2 over vocab. One warp per row.
// ---------------------------------------------------------------------------
__global__ void lse_kernel(const float* __restrict__ logits) {
    int w = (blockIdx.x * blockDim.x + threadIdx.x) >> 5;
    int lane = threadIdx.x & 31;
    if (w >= Tt * Bb) return;
    const float* row = logits + (size_t)w * Vv;
    float y[6];
    float m = NEGV;
#pragma unroll
    for (int i = 0; i < 6; i++) {
        int v = lane + 32 * i;
        y[i] = (v < Vv) ? row[v] * LOG2E : NEGV;
        m = fmaxf(m, y[i]);
    }
#pragma unroll
    for (int o = 16; o > 0; o >>= 1) m = fmaxf(m, __shfl_xor_sync(0xffffffffu, m, o));
    float sv = 0.f;
#pragma unroll
    for (int i = 0; i < 6; i++) sv += ex2f_(y[i] - m);
#pragma unroll
    for (int o = 16; o > 0; o >>= 1) sv += __shfl_xor_sync(0xffffffffu, sv, o);
    if (lane == 0) {
        int t = w / Bb, b = w % Bb;
        g_lse2[b * Tt + t] = m + lg2f_(sv);
    }
}

// ---------------------------------------------------------------------------
// Kernel 2: CTC forward on RAW log2-logits. One CTA (9 warps) per utterance;
// lane owns ONE pair (blank 2p, label 2p+1); 9-pair left halo; 9 steps per
// barrier. Chain-optimized lae3 (pre-shfl M1/m1); triple-buffered row staging
// with STS issued at superstep start (drained long before the barrier).
// ---------------------------------------------------------------------------
__global__ void __launch_bounds__(THR, 1) ctc_alpha_kernel(
    const float* __restrict__ logits,
    const int*   __restrict__ labels,
    const int*   __restrict__ act_lens,
    const int*   __restrict__ label_lens)
{
    const int b    = blockIdx.x;
    const int tid  = threadIdx.x;
    const int lane = tid & 31;
    const int w    = tid >> 5;

    __shared__ float2 snap[2][NSNAP];
    __shared__ float  rbuf[3][UU * RSTR];

    const int act_len   = act_lens[b];
    const int label_len = label_lens[b];

    const int  p = OWNW * w - HALO + lane;
    const bool owner = (lane >= HALO) && (p < NSNAP);

    const int  pc   = min(max(p, 0), Lmax - 1);
    const int  lab  = labels[b * Lmax + pc];
    const bool allow = (p > 0) && (p <= Lmax - 1) &&
                       (lab != labels[b * Lmax + max(pc - 1, 0)]);
    const bool vE = (p >= 0) && (p <= label_len);
    const bool vO = (p >= 0) && (p <  label_len);

    const float* base = logits + (size_t)b * Vv;
    const size_t gstr = (size_t)Bb * Vv;

    // fixed staging index map
    int su[NSTG], svv[NSTG]; bool sa[NSTG];
#pragma unroll
    for (int i = 0; i < NSTG; i++) {
        int idx = tid + i * THR;
        sa[i]  = idx < UU * Vv;
        su[i]  = idx / Vv;
        svv[i] = idx - su[i] * Vv;
    }

    for (int i = tid; i < NSNAP; i += THR) {
        snap[0][i] = make_float2(NEGV, NEGV);
        snap[1][i] = make_float2(NEGV, NEGV);
    }
    // preamble: stage rows 1..9 into rbuf[0]; LDG rows 10..18 into g[]
    float g[NSTG];
#pragma unroll
    for (int i = 0; i < NSTG; i++) {
        if (sa[i]) {
            int tr = 1 + su[i]; if (tr > Tt - 1) tr = Tt - 1;
            rbuf[0][su[i] * RSTR + svv[i]] = base[(size_t)tr * gstr + svv[i]] * LOG2E;
            int tr2 = 1 + UU + su[i]; if (tr2 > Tt - 1) tr2 = Tt - 1;
            g[i] = base[(size_t)tr2 * gstr + svv[i]];
        }
    }
    __syncthreads();
    if (p == 0 && owner) {
        float aE0 = base[0] * LOG2E;
        float aO0 = (label_len > 0) ? base[lab] * LOG2E : NEGV;
        snap[0][0] = make_float2(aE0, aO0);
    }
    __syncthreads();

    int scur = 0, rcur = 0;
    for (int t0 = 1; t0 < act_len; t0 += UU) {
        const int rnxt = (rcur + 1) % 3;   // buffer for next superstep
        // preload this superstep's log-probs
        const float* rb = rbuf[rcur];
        float lpB[UU], lpL[UU];
#pragma unroll
        for (int u = 0; u < UU; u++) {
            lpB[u] = rb[u * RSTR];
            lpL[u] = rb[u * RSTR + lab];
        }
        // EARLY STS: rows for next superstep (LDG'd last superstep)
#pragma unroll
        for (int i = 0; i < NSTG; i++)
            if (sa[i]) rbuf[rnxt][su[i] * RSTR + svv[i]] = g[i] * LOG2E;
        // LDG rows for superstep after next
#pragma unroll
        for (int i = 0; i < NSTG; i++) {
            if (sa[i]) {
                int tr = t0 + 2 * UU + su[i]; if (tr > Tt - 1) tr = Tt - 1;
                g[i] = base[(size_t)tr * gstr + svv[i]];
            }
        }

        float2 P = (p >= 0) ? snap[scur][p] : make_float2(NEGV, NEGV);
        float aE = P.x, aO = P.y;

#pragma unroll
        for (int u = 0; u < UU; u++) {
            const bool live = (t0 + u) < act_len;
            // issue shfl first; M1/m1 precompute overlaps its latency
            float aOp = __shfl_up_sync(0xffffffffu, aO, 1);
            float M1 = fmaxf(aO, aE);
            float m1 = fminf(aO, aE);
            if (lane == 0) aOp = NEGV;
            float c  = allow ? aOp : NEGV;

            // nE = lae2(aE, aOp) + lpB   (off the carried chain)
            float ME = fmaxf(aE, aOp), mE = fminf(aE, aOp);
            float nE = ME + lg2f_(1.0f + ex2f_(mE - ME)) + lpB[u];

            // nO = lae3(aO, aE, c) + lpL  (short post-shfl depth)
            float M2 = fmaxf(M1, c), m2 = fminf(M1, c);
            float nO = M2 + lg2f_(1.0f + ex2f_(m1 - M2) + ex2f_(m2 - M2)) + lpL[u];

            if (live) {
                aE = vE ? nE : NEGV;
                aO = vO ? nO : NEGV;
            }
        }

        if (owner) snap[scur ^ 1][p] = make_float2(aE, aO);
        __syncthreads();
        scur ^= 1;
        rcur = rnxt;
    }

    if (tid == 0) {
        float al = snap[scur][label_len].x;                        // state 2L
        float ap = (label_len > 0) ? snap[scur][label_len - 1].y   // state 2L-1
                                   : NEGV;
        g_llraw[b] = lae2_(al, ap);
    }
}

// ---------------------------------------------------------------------------
// Kernel 3: per-b normalization correction (fp64 sum of lse2) + loss
// ---------------------------------------------------------------------------
__global__ void finalize_kernel(const int* __restrict__ act_lens) {
    const int b = blockIdx.x, tid = threadIdx.x;
    const int n = act_lens[b];
    const float* pr = g_lse2 + (size_t)b * Tt;
    double sd = 0.0;
    for (int t = tid; t < n; t += 256) sd += (double)pr[t];
    __shared__ double red[256];
    red[tid] = sd; __syncthreads();
    for (int o = 128; o > 0; o >>= 1) {
        if (tid < o) red[tid] += red[tid + o];
        __syncthreads();
    }
    if (tid == 0)
        g_losses[b] = (float)((red[0] - (double)g_llraw[b]) * (double)LN2);
}

// ---------------------------------------------------------------------------
// Kernel 4: total = sum(losses) / sum(act_lens)
// ---------------------------------------------------------------------------
__global__ void reduce_kernel(const int* __restrict__ act_lens,
                              float* __restrict__ out)
{
    int lane = threadIdx.x;
    float l = g_losses[lane] + g_losses[lane + 32];
    float n = (float)act_lens[lane] + (float)act_lens[lane + 32];
#pragma unroll
    for (int o = 16; o > 0; o >>= 1) {
        l += __shfl_xor_sync(0xffffffffu, l, o);
        n += __shfl_xor_sync(0xffffffffu, n, o);
    }
    if (lane == 0) out[0] = l / n;
}

extern "C" void kernel_launch(void* const* d_in, const int* in_sizes, int n_in,
                              void* d_out, int out_size)
{
    const float* logits     = (const float*)d_in[0];
    const int*   labels     = (const int*)  d_in[1];
    const int*   act_lens   = (const int*)  d_in[2];
    const int*   label_lens = (const int*)  d_in[3];

    const int rows = Tt * Bb;
    lse_kernel<<<(rows * 32 + 255) / 256, 256>>>(logits);
    ctc_alpha_kernel<<<Bb, THR>>>(logits, labels, act_lens, label_lens);
    finalize_kernel<<<Bb, 256>>>(act_lens);
    reduce_kernel<<<1, 32>>>(act_lens, (float*)d_out);
}